// round 3
// baseline (speedup 1.0000x reference)
#include <cuda_runtime.h>
#include <math.h>

// Problem constants
#define BSZ 8
#define HH 256
#define WW 256
#define C1 64
#define NBR 6

typedef unsigned long long u64;

// Packed f32x2 helpers (FFMA2 — PTX-only, ptxas never emits from C++)
__device__ __forceinline__ u64 pk2(float lo, float hi) {
    u64 r; asm("mov.b64 %0, {%1, %2};" : "=l"(r) : "f"(lo), "f"(hi)); return r;
}
__device__ __forceinline__ void upk2(float& lo, float& hi, u64 v) {
    asm("mov.b64 {%0, %1}, %2;" : "=f"(lo), "=f"(hi) : "l"(v));
}
__device__ __forceinline__ u64 ffma2(u64 a, u64 b, u64 c) {
    u64 d; asm("fma.rn.f32x2 %0, %1, %2, %3;" : "=l"(d) : "l"(a), "l"(b), "l"(c)); return d;
}

// Scratch: weighted neighbor frames (B, 6, H, W) = 12.6 MB
__device__ float g_weighted[BSZ * NBR * HH * WW];

// Tile geometry: 256 threads, 16x16 thread grid, 4 px/thread in x
#define TW 64
#define TH 16

// ---------------------------------------------------------------------------
// Kernel A: fused conv1(2->64,3x3)+ReLU+conv2(64->1,1x1)+sigmoid+gate
// Packed f32x2 math: pixel pairs (0,1) and (2,3) per thread.
// ---------------------------------------------------------------------------
__global__ __launch_bounds__(256, 2) void branch_kernel(
    const float* __restrict__ x,
    const float* __restrict__ W1,
    const float* __restrict__ b1,
    const float* __restrict__ W2,
    const float* __restrict__ b2)
{
    __shared__ float sB[TH + 2][TW + 4];   // base tile + halo (68 = 272B rows, 16B aligned)
    __shared__ float sC[TH + 2][TW + 4];   // check tile + halo
    __shared__ u64 sW1b[C1][9];            // conv1 weights (dup-packed), base channel
    __shared__ u64 sW1c[C1][9];            // conv1 weights (dup-packed), check channel
    __shared__ u64 sB1[C1];                // bias (dup-packed)
    __shared__ u64 sW2[C1];                // 1x1 weights (dup-packed)

    const int bz  = blockIdx.z;
    const int b   = bz / NBR;
    const int n   = bz % NBR;
    const int ty0 = blockIdx.y * TH;
    const int tx0 = blockIdx.x * TW;
    const int tid = threadIdx.x;

    const int checkCh = (n < 3) ? n : (n + 1);
    const int bi = (n < 3) ? 0 : 1;     // pair ch index that holds base

    const float* __restrict__ base = x + (size_t)(b * 7 + 3) * (HH * WW);
    const float* __restrict__ chk  = x + (size_t)(b * 7 + checkCh) * (HH * WW);

    // Stage dup-packed weights
    for (int i = tid; i < C1 * 9; i += 256) {
        int c = i / 9, k = i % 9;
        float wb = W1[((n * C1 + c) * 2 + bi) * 9 + k];
        float wc = W1[((n * C1 + c) * 2 + (1 - bi)) * 9 + k];
        sW1b[c][k] = pk2(wb, wb);
        sW1c[c][k] = pk2(wc, wc);
    }
    if (tid < C1) {
        float bv = b1[n * C1 + tid];
        float wv = W2[n * C1 + tid];
        sB1[tid] = pk2(bv, bv);
        sW2[tid] = pk2(wv, wv);
    }

    // Stage input tiles with 1-px zero halo
    for (int i = tid; i < (TH + 2) * (TW + 2); i += 256) {
        int r  = i / (TW + 2);
        int cc = i % (TW + 2);
        int gy = ty0 + r - 1;
        int gx = tx0 + cc - 1;
        bool ok = (gy >= 0) && (gy < HH) && (gx >= 0) && (gx < WW);
        sB[r][cc] = ok ? base[gy * WW + gx] : 0.0f;
        sC[r][cc] = ok ? chk[gy * WW + gx] : 0.0f;
    }
    __syncthreads();

    const int lx = tid & 15;
    const int ly = tid >> 4;
    const int px = lx * 4;

    // Pre-packed overlapping tap pairs: tp[r][j] = (t[j], t[j+1]), j=0..4.
    // Pixel pair (0,1) at kernel col k uses tp[r][k]; pair (2,3) uses tp[r][k+2].
    u64 tBp[3][5], tCp[3][5];
    float c1v, c2v, c3v, c4v;   // center taps (row 1, cols 1..4) for the gate multiply
#pragma unroll
    for (int r = 0; r < 3; r++) {
        const float* rb = &sB[ly + r][px];
        const float* rc = &sC[ly + r][px];
        float4 b4 = *reinterpret_cast<const float4*>(rb);
        float2 b2v = *reinterpret_cast<const float2*>(rb + 4);
        float4 c4 = *reinterpret_cast<const float4*>(rc);
        float2 c2 = *reinterpret_cast<const float2*>(rc + 4);
        float tb[6] = {b4.x, b4.y, b4.z, b4.w, b2v.x, b2v.y};
        float tc[6] = {c4.x, c4.y, c4.z, c4.w, c2.x, c2.y};
#pragma unroll
        for (int j = 0; j < 5; j++) {
            tBp[r][j] = pk2(tb[j], tb[j + 1]);
            tCp[r][j] = pk2(tc[j], tc[j + 1]);
        }
        if (r == 1) { c1v = tc[1]; c2v = tc[2]; c3v = tc[3]; c4v = tc[4]; }
    }

    u64 s01 = pk2(0.f, 0.f), s23 = pk2(0.f, 0.f);

#pragma unroll 4
    for (int c = 0; c < C1; c++) {
        u64 a01 = sB1[c];
        u64 a23 = a01;
#pragma unroll
        for (int r = 0; r < 3; r++)
#pragma unroll
            for (int k = 0; k < 3; k++) {
                const u64 wb = sW1b[c][r * 3 + k];
                const u64 wc = sW1c[c][r * 3 + k];
                a01 = ffma2(wb, tBp[r][k],     a01);
                a01 = ffma2(wc, tCp[r][k],     a01);
                a23 = ffma2(wb, tBp[r][k + 2], a23);
                a23 = ffma2(wc, tCp[r][k + 2], a23);
            }
        // ReLU on alu pipe (FMNMX), repack, 1x1 reduce on fma pipe
        float a0, a1, a2, a3;
        upk2(a0, a1, a01);
        upk2(a2, a3, a23);
        a0 = fmaxf(a0, 0.f); a1 = fmaxf(a1, 0.f);
        a2 = fmaxf(a2, 0.f); a3 = fmaxf(a3, 0.f);
        const u64 w2 = sW2[c];
        s01 = ffma2(w2, pk2(a0, a1), s01);
        s23 = ffma2(w2, pk2(a2, a3), s23);
    }

    float s0, s1, s2, s3;
    upk2(s0, s1, s01);
    upk2(s2, s3, s23);
    const float bb2 = b2[n];
    const float g0 = 1.f / (1.f + __expf(-(s0 + bb2)));
    const float g1 = 1.f / (1.f + __expf(-(s1 + bb2)));
    const float g2 = 1.f / (1.f + __expf(-(s2 + bb2)));
    const float g3 = 1.f / (1.f + __expf(-(s3 + bb2)));

    const int gy = ty0 + ly;
    float* o = g_weighted + ((size_t)(b * NBR + n) * HH + gy) * WW + tx0 + px;
    float4 w4;
    w4.x = g0 * c1v;
    w4.y = g1 * c2v;
    w4.z = g2 * c3v;
    w4.w = g3 * c4v;
    *reinterpret_cast<float4*>(o) = w4;
}

// ---------------------------------------------------------------------------
// Kernel B: final 7->7 3x3 conv, packed f32x2
// ---------------------------------------------------------------------------
__global__ __launch_bounds__(256, 2) void merge_kernel(
    const float* __restrict__ x,
    const float* __restrict__ Wm,
    const float* __restrict__ bm,
    float* __restrict__ out)
{
    __shared__ float sIn[7][TH + 2][TW + 4];
    __shared__ u64 sW[7 * 7 * 9];          // dup-packed merge weights
    __shared__ float sbm[7];

    const int b   = blockIdx.z;
    const int ty0 = blockIdx.y * TH;
    const int tx0 = blockIdx.x * TW;
    const int tid = threadIdx.x;

    for (int i = tid; i < 7 * 7 * 9; i += 256) {
        float w = Wm[i];
        sW[i] = pk2(w, w);
    }
    if (tid < 7) sbm[tid] = bm[tid];

    const int tile = (TH + 2) * (TW + 2);
    for (int i = tid; i < 7 * tile; i += 256) {
        int ch  = i / tile;
        int rem = i % tile;
        int r   = rem / (TW + 2);
        int cc  = rem % (TW + 2);
        int gy  = ty0 + r - 1;
        int gx  = tx0 + cc - 1;
        float v = 0.f;
        if (gy >= 0 && gy < HH && gx >= 0 && gx < WW) {
            if (ch == 3) {
                v = x[(size_t)(b * 7 + 3) * (HH * WW) + gy * WW + gx];
            } else {
                int m = (ch < 3) ? ch : (ch - 1);
                v = g_weighted[((size_t)(b * NBR + m) * HH + gy) * WW + gx];
            }
        }
        sIn[ch][r][cc] = v;
    }
    __syncthreads();

    const int lx = tid & 15;
    const int ly = tid >> 4;
    const int px = lx * 4;

    u64 acc01[7], acc23[7];
#pragma unroll
    for (int co = 0; co < 7; co++) {
        const float bv = sbm[co];
        acc01[co] = pk2(bv, bv);
        acc23[co] = acc01[co];
    }

#pragma unroll
    for (int ci = 0; ci < 7; ci++) {
        u64 tp[3][5];
#pragma unroll
        for (int r = 0; r < 3; r++) {
            const float* rp = &sIn[ci][ly + r][px];
            float4 v4 = *reinterpret_cast<const float4*>(rp);
            float2 v2 = *reinterpret_cast<const float2*>(rp + 4);
            float t[6] = {v4.x, v4.y, v4.z, v4.w, v2.x, v2.y};
#pragma unroll
            for (int j = 0; j < 5; j++)
                tp[r][j] = pk2(t[j], t[j + 1]);
        }

#pragma unroll
        for (int co = 0; co < 7; co++) {
#pragma unroll
            for (int r = 0; r < 3; r++)
#pragma unroll
                for (int k = 0; k < 3; k++) {
                    const u64 w = sW[(co * 7 + ci) * 9 + r * 3 + k];
                    acc01[co] = ffma2(w, tp[r][k],     acc01[co]);
                    acc23[co] = ffma2(w, tp[r][k + 2], acc23[co]);
                }
        }
    }

    const int gy = ty0 + ly;
#pragma unroll
    for (int co = 0; co < 7; co++) {
        float* o = out + ((size_t)(b * 7 + co) * HH + gy) * WW + tx0 + px;
        float4 v4;
        upk2(v4.x, v4.y, acc01[co]);
        upk2(v4.z, v4.w, acc23[co]);
        *reinterpret_cast<float4*>(o) = v4;
    }
}

// ---------------------------------------------------------------------------
extern "C" void kernel_launch(void* const* d_in, const int* in_sizes, int n_in,
                              void* d_out, int out_size)
{
    const float* x  = (const float*)d_in[0];   // (8, 7, 256, 256)
    const float* W1 = (const float*)d_in[1];   // (6, 64, 2, 3, 3)
    const float* b1 = (const float*)d_in[2];   // (6, 64)
    const float* W2 = (const float*)d_in[3];   // (6, 1, 64, 1, 1)
    const float* b2 = (const float*)d_in[4];   // (6, 1)
    const float* Wm = (const float*)d_in[5];   // (7, 7, 3, 3)
    const float* bm = (const float*)d_in[6];   // (7,)

    dim3 grid1(WW / TW, HH / TH, BSZ * NBR);   // 4 x 16 x 48
    branch_kernel<<<grid1, 256>>>(x, W1, b1, W2, b2);

    dim3 grid2(WW / TW, HH / TH, BSZ);         // 4 x 16 x 8
    merge_kernel<<<grid2, 256>>>(x, Wm, bm, (float*)d_out);
}

// round 4
// speedup vs baseline: 1.1551x; 1.1551x over previous
#include <cuda_runtime.h>
#include <math.h>

// Problem constants
#define BSZ 8
#define HH 256
#define WW 256
#define C1 64
#define NBR 6

// Scratch: weighted neighbor frames (B, 6, H, W) = 12.6 MB
__device__ float g_weighted[BSZ * NBR * HH * WW];

// ---------------------------------------------------------------------------
// Kernel A geometry: 256 threads as 16x16; each thread computes 8 px in x.
// Tile = 128 x 16 outputs.
// ---------------------------------------------------------------------------
#define TWA 128
#define THA 16

__global__ __launch_bounds__(256, 2) void branch_kernel(
    const float* __restrict__ x,
    const float* __restrict__ W1,
    const float* __restrict__ b1,
    const float* __restrict__ W2,
    const float* __restrict__ b2)
{
    __shared__ float sB[THA + 2][TWA + 4];   // 18 x 132 (row = 528B, 16B-aligned)
    __shared__ float sC[THA + 2][TWA + 4];
    // Per-channel packed weights: [0..8]=wb(9), [9..17]=wc(9), [18]=b1, [19]=w2, pad->24
    __shared__ float sWp[C1][24];

    const int bz  = blockIdx.z;
    const int b   = bz / NBR;
    const int n   = bz % NBR;
    const int ty0 = blockIdx.y * THA;
    const int tx0 = blockIdx.x * TWA;
    const int tid = threadIdx.x;

    const int checkCh = (n < 3) ? n : (n + 1);
    const int bi = (n < 3) ? 0 : 1;   // pair channel that holds base

    const float* __restrict__ base = x + (size_t)(b * 7 + 3) * (HH * WW);
    const float* __restrict__ chk  = x + (size_t)(b * 7 + checkCh) * (HH * WW);

    // Stage packed weights
    for (int i = tid; i < C1 * 9; i += 256) {
        int c = i / 9, k = i % 9;
        sWp[c][k]     = W1[((n * C1 + c) * 2 + bi) * 9 + k];
        sWp[c][9 + k] = W1[((n * C1 + c) * 2 + (1 - bi)) * 9 + k];
    }
    if (tid < C1) {
        sWp[tid][18] = b1[n * C1 + tid];
        sWp[tid][19] = W2[n * C1 + tid];
    }

    // Stage input tiles with 1-px zero halo: 18 x 130 elements each
    for (int i = tid; i < (THA + 2) * (TWA + 2); i += 256) {
        int r  = i / (TWA + 2);
        int cc = i % (TWA + 2);
        int gy = ty0 + r - 1;
        int gx = tx0 + cc - 1;
        bool ok = (gy >= 0) && (gy < HH) && (gx >= 0) && (gx < WW);
        sB[r][cc] = ok ? base[gy * WW + gx] : 0.0f;
        sC[r][cc] = ok ? chk[gy * WW + gx] : 0.0f;
    }
    __syncthreads();

    const int lx = tid & 15;
    const int ly = tid >> 4;
    const int px = lx * 8;

    // Register taps: 3 rows x 10 cols per input (8 px + 2 halo)
    float tB[3][10], tC[3][10];
#pragma unroll
    for (int r = 0; r < 3; r++) {
        const float* rb = &sB[ly + r][px];
        const float* rc = &sC[ly + r][px];
        float4 b0 = *reinterpret_cast<const float4*>(rb);
        float4 b1v = *reinterpret_cast<const float4*>(rb + 4);
        float2 b2v = *reinterpret_cast<const float2*>(rb + 8);
        float4 c0 = *reinterpret_cast<const float4*>(rc);
        float4 c1 = *reinterpret_cast<const float4*>(rc + 4);
        float2 c2 = *reinterpret_cast<const float2*>(rc + 8);
        tB[r][0]=b0.x; tB[r][1]=b0.y; tB[r][2]=b0.z; tB[r][3]=b0.w;
        tB[r][4]=b1v.x; tB[r][5]=b1v.y; tB[r][6]=b1v.z; tB[r][7]=b1v.w;
        tB[r][8]=b2v.x; tB[r][9]=b2v.y;
        tC[r][0]=c0.x; tC[r][1]=c0.y; tC[r][2]=c0.z; tC[r][3]=c0.w;
        tC[r][4]=c1.x; tC[r][5]=c1.y; tC[r][6]=c1.z; tC[r][7]=c1.w;
        tC[r][8]=c2.x; tC[r][9]=c2.y;
    }

    float s[8];
#pragma unroll
    for (int p = 0; p < 8; p++) s[p] = 0.0f;

#pragma unroll 1
    for (int c = 0; c < C1; c++) {
        // 5 x LDS.128 fetch the whole channel's weights
        const float4 wA = *reinterpret_cast<const float4*>(&sWp[c][0]);
        const float4 wB = *reinterpret_cast<const float4*>(&sWp[c][4]);
        const float4 wC = *reinterpret_cast<const float4*>(&sWp[c][8]);
        const float4 wD = *reinterpret_cast<const float4*>(&sWp[c][12]);
        const float4 wE = *reinterpret_cast<const float4*>(&sWp[c][16]);
        const float wb[9] = {wA.x, wA.y, wA.z, wA.w, wB.x, wB.y, wB.z, wB.w, wC.x};
        const float wc[9] = {wC.y, wC.z, wC.w, wD.x, wD.y, wD.z, wD.w, wE.x, wE.y};
        const float bb = wE.z;
        const float w2 = wE.w;

        float a[8];
#pragma unroll
        for (int p = 0; p < 8; p++) a[p] = bb;

#pragma unroll
        for (int r = 0; r < 3; r++)
#pragma unroll
            for (int k = 0; k < 3; k++) {
                const float u = wb[r * 3 + k];
                const float v = wc[r * 3 + k];
#pragma unroll
                for (int p = 0; p < 8; p++)
                    a[p] = fmaf(u, tB[r][k + p], fmaf(v, tC[r][k + p], a[p]));
            }

#pragma unroll
        for (int p = 0; p < 8; p++)
            s[p] = fmaf(w2, fmaxf(a[p], 0.0f), s[p]);
    }

    const float bb2 = b2[n];
    const int gy = ty0 + ly;
    float* o = g_weighted + ((size_t)(b * NBR + n) * HH + gy) * WW + tx0 + px;

    float w8[8];
#pragma unroll
    for (int p = 0; p < 8; p++) {
        const float g = 1.0f / (1.0f + __expf(-(s[p] + bb2)));
        w8[p] = g * tC[1][p + 1];   // gate * center check tap
    }
    float4 v0, v1;
    v0.x = w8[0]; v0.y = w8[1]; v0.z = w8[2]; v0.w = w8[3];
    v1.x = w8[4]; v1.y = w8[5]; v1.z = w8[6]; v1.w = w8[7];
    *reinterpret_cast<float4*>(o)     = v0;
    *reinterpret_cast<float4*>(o + 4) = v1;
}

// ---------------------------------------------------------------------------
// Kernel B: final 7->7 3x3 conv. 128 threads (8x16), 4 px/thread, 32x16 tile.
// High occupancy (small blocks) to fix the latency-bound profile.
// ---------------------------------------------------------------------------
#define TWB 32
#define THB 16

__global__ __launch_bounds__(128, 4) void merge_kernel(
    const float* __restrict__ x,
    const float* __restrict__ Wm,
    const float* __restrict__ bm,
    float* __restrict__ out)
{
    __shared__ float sIn[7][THB + 2][TWB + 4];   // 7 x 18 x 36 (row 144B, 16B-aligned)
    __shared__ float sW[7][7][12];               // 9 weights padded to 12 (48B, 16B-aligned)
    __shared__ float sbm[7];

    const int b   = blockIdx.z;
    const int ty0 = blockIdx.y * THB;
    const int tx0 = blockIdx.x * TWB;
    const int tid = threadIdx.x;

    for (int i = tid; i < 7 * 7 * 9; i += 128) {
        int pair = i / 9, k = i % 9;
        sW[pair / 7][pair % 7][k] = Wm[i];
    }
    if (tid < 7) sbm[tid] = bm[tid];

    const int tile = (THB + 2) * (TWB + 2);      // 18 * 34 = 612
    for (int i = tid; i < 7 * tile; i += 128) {
        int ch  = i / tile;
        int rem = i % tile;
        int r   = rem / (TWB + 2);
        int cc  = rem % (TWB + 2);
        int gy  = ty0 + r - 1;
        int gx  = tx0 + cc - 1;
        float v = 0.0f;
        if (gy >= 0 && gy < HH && gx >= 0 && gx < WW) {
            if (ch == 3) {
                v = x[(size_t)(b * 7 + 3) * (HH * WW) + gy * WW + gx];
            } else {
                int m = (ch < 3) ? ch : (ch - 1);
                v = g_weighted[((size_t)(b * NBR + m) * HH + gy) * WW + gx];
            }
        }
        sIn[ch][r][cc] = v;
    }
    __syncthreads();

    const int lx = tid & 7;
    const int ly = tid >> 3;
    const int px = lx * 4;

    float acc[7][4];
#pragma unroll
    for (int co = 0; co < 7; co++) {
        const float bv = sbm[co];
        acc[co][0] = bv; acc[co][1] = bv; acc[co][2] = bv; acc[co][3] = bv;
    }

#pragma unroll
    for (int ci = 0; ci < 7; ci++) {
        float t[3][6];
#pragma unroll
        for (int r = 0; r < 3; r++) {
            const float* rp = &sIn[ci][ly + r][px];
            float4 v4 = *reinterpret_cast<const float4*>(rp);
            float2 v2 = *reinterpret_cast<const float2*>(rp + 4);
            t[r][0] = v4.x; t[r][1] = v4.y; t[r][2] = v4.z;
            t[r][3] = v4.w; t[r][4] = v2.x; t[r][5] = v2.y;
        }

#pragma unroll
        for (int co = 0; co < 7; co++) {
            const float4 wA = *reinterpret_cast<const float4*>(&sW[co][ci][0]);
            const float4 wB = *reinterpret_cast<const float4*>(&sW[co][ci][4]);
            const float4 wC = *reinterpret_cast<const float4*>(&sW[co][ci][8]);
            const float w[9] = {wA.x, wA.y, wA.z, wA.w, wB.x, wB.y, wB.z, wB.w, wC.x};
#pragma unroll
            for (int r = 0; r < 3; r++)
#pragma unroll
                for (int k = 0; k < 3; k++) {
                    const float ww = w[r * 3 + k];
                    acc[co][0] = fmaf(ww, t[r][k],     acc[co][0]);
                    acc[co][1] = fmaf(ww, t[r][k + 1], acc[co][1]);
                    acc[co][2] = fmaf(ww, t[r][k + 2], acc[co][2]);
                    acc[co][3] = fmaf(ww, t[r][k + 3], acc[co][3]);
                }
        }
    }

    const int gy = ty0 + ly;
#pragma unroll
    for (int co = 0; co < 7; co++) {
        float* o = out + ((size_t)(b * 7 + co) * HH + gy) * WW + tx0 + px;
        float4 v4;
        v4.x = acc[co][0]; v4.y = acc[co][1]; v4.z = acc[co][2]; v4.w = acc[co][3];
        *reinterpret_cast<float4*>(o) = v4;
    }
}

// ---------------------------------------------------------------------------
extern "C" void kernel_launch(void* const* d_in, const int* in_sizes, int n_in,
                              void* d_out, int out_size)
{
    const float* x  = (const float*)d_in[0];   // (8, 7, 256, 256)
    const float* W1 = (const float*)d_in[1];   // (6, 64, 2, 3, 3)
    const float* b1 = (const float*)d_in[2];   // (6, 64)
    const float* W2 = (const float*)d_in[3];   // (6, 1, 64, 1, 1)
    const float* b2 = (const float*)d_in[4];   // (6, 1)
    const float* Wm = (const float*)d_in[5];   // (7, 7, 3, 3)
    const float* bm = (const float*)d_in[6];   // (7,)

    dim3 grid1(WW / TWA, HH / THA, BSZ * NBR);   // 2 x 16 x 48 = 1536
    branch_kernel<<<grid1, 256>>>(x, W1, b1, W2, b2);

    dim3 grid2(WW / TWB, HH / THB, BSZ);         // 8 x 16 x 8 = 1024
    merge_kernel<<<grid2, 128>>>(x, Wm, bm, (float*)d_out);
}

// round 6
// speedup vs baseline: 1.2423x; 1.0755x over previous
#include <cuda_runtime.h>
#include <math.h>

// Problem constants
#define BSZ 8
#define HH 256
#define WW 256
#define C1 64
#define NBR 6

// Scratch: weighted neighbor frames (B, 6, H, W) = 12.6 MB
__device__ float g_weighted[BSZ * NBR * HH * WW];

// ---------------------------------------------------------------------------
// Kernel A: fused conv1(2->64,3x3)+ReLU+conv2(64->1,1x1)+sigmoid+gate
// 128 threads as 16x8; 4 px/thread; tile = 64x8.
// ---------------------------------------------------------------------------
#define TWA 64
#define THA 8

__global__ __launch_bounds__(128) void branch_kernel(
    const float* __restrict__ x,
    const float* __restrict__ W1,
    const float* __restrict__ b1,
    const float* __restrict__ W2,
    const float* __restrict__ b2)
{
    __shared__ float sB[THA + 2][TWA + 4];   // 10 x 68 rows (272B, 16B-aligned)
    __shared__ float sC[THA + 2][TWA + 4];
    // Per-channel packed weights: [0..8]=wb, [9..17]=wc, [18]=b1, [19]=w2, pad->24
    __shared__ float sWp[C1][24];

    const int bz  = blockIdx.z;
    const int b   = bz / NBR;
    const int n   = bz % NBR;
    const int ty0 = blockIdx.y * THA;
    const int tx0 = blockIdx.x * TWA;
    const int tid = threadIdx.x;

    const int checkCh = (n < 3) ? n : (n + 1);
    const int bi = (n < 3) ? 0 : 1;   // pair channel that holds base

    const float* __restrict__ base = x + (size_t)(b * 7 + 3) * (HH * WW);
    const float* __restrict__ chk  = x + (size_t)(b * 7 + checkCh) * (HH * WW);

    // Stage packed weights
    for (int i = tid; i < C1 * 9; i += 128) {
        int c = i / 9, k = i % 9;
        sWp[c][k]     = W1[((n * C1 + c) * 2 + bi) * 9 + k];
        sWp[c][9 + k] = W1[((n * C1 + c) * 2 + (1 - bi)) * 9 + k];
    }
    if (tid < C1) {
        sWp[tid][18] = b1[n * C1 + tid];
        sWp[tid][19] = W2[n * C1 + tid];
    }

    // Stage input tiles with 1-px zero halo: 10 x 66 elements each
    for (int i = tid; i < (THA + 2) * (TWA + 2); i += 128) {
        int r  = i / (TWA + 2);
        int cc = i % (TWA + 2);
        int gy = ty0 + r - 1;
        int gx = tx0 + cc - 1;
        bool ok = (gy >= 0) && (gy < HH) && (gx >= 0) && (gx < WW);
        sB[r][cc] = ok ? base[gy * WW + gx] : 0.0f;
        sC[r][cc] = ok ? chk[gy * WW + gx] : 0.0f;
    }
    __syncthreads();

    const int lx = tid & 15;
    const int ly = tid >> 4;
    const int px = lx * 4;

    // Register taps: 3 rows x 6 cols per input (4 px + 2 halo)
    float tB[3][6], tC[3][6];
#pragma unroll
    for (int r = 0; r < 3; r++) {
        const float* rb = &sB[ly + r][px];
        const float* rc = &sC[ly + r][px];
        float4 b4 = *reinterpret_cast<const float4*>(rb);
        float2 b2v = *reinterpret_cast<const float2*>(rb + 4);
        float4 c4 = *reinterpret_cast<const float4*>(rc);
        float2 c2 = *reinterpret_cast<const float2*>(rc + 4);
        tB[r][0]=b4.x; tB[r][1]=b4.y; tB[r][2]=b4.z; tB[r][3]=b4.w;
        tB[r][4]=b2v.x; tB[r][5]=b2v.y;
        tC[r][0]=c4.x; tC[r][1]=c4.y; tC[r][2]=c4.z; tC[r][3]=c4.w;
        tC[r][4]=c2.x; tC[r][5]=c2.y;
    }

    float s0 = 0.f, s1 = 0.f, s2 = 0.f, s3 = 0.f;

#pragma unroll 2
    for (int c = 0; c < C1; c++) {
        const float4 wA = *reinterpret_cast<const float4*>(&sWp[c][0]);
        const float4 wB = *reinterpret_cast<const float4*>(&sWp[c][4]);
        const float4 wC = *reinterpret_cast<const float4*>(&sWp[c][8]);
        const float4 wD = *reinterpret_cast<const float4*>(&sWp[c][12]);
        const float4 wE = *reinterpret_cast<const float4*>(&sWp[c][16]);
        const float wb[9] = {wA.x, wA.y, wA.z, wA.w, wB.x, wB.y, wB.z, wB.w, wC.x};
        const float wc[9] = {wC.y, wC.z, wC.w, wD.x, wD.y, wD.z, wD.w, wE.x, wE.y};
        const float bb = wE.z;
        const float w2 = wE.w;

        // Bias folded into the first (r=0,k=0) FMA — no MOV init
        float a0 = fmaf(wb[0], tB[0][0], fmaf(wc[0], tC[0][0], bb));
        float a1 = fmaf(wb[0], tB[0][1], fmaf(wc[0], tC[0][1], bb));
        float a2 = fmaf(wb[0], tB[0][2], fmaf(wc[0], tC[0][2], bb));
        float a3 = fmaf(wb[0], tB[0][3], fmaf(wc[0], tC[0][3], bb));

#pragma unroll
        for (int r = 0; r < 3; r++)
#pragma unroll
            for (int k = 0; k < 3; k++) {
                if (r == 0 && k == 0) continue;
                const float u = wb[r * 3 + k];
                const float v = wc[r * 3 + k];
                a0 = fmaf(u, tB[r][k],     fmaf(v, tC[r][k],     a0));
                a1 = fmaf(u, tB[r][k + 1], fmaf(v, tC[r][k + 1], a1));
                a2 = fmaf(u, tB[r][k + 2], fmaf(v, tC[r][k + 2], a2));
                a3 = fmaf(u, tB[r][k + 3], fmaf(v, tC[r][k + 3], a3));
            }

        s0 = fmaf(w2, fmaxf(a0, 0.f), s0);
        s1 = fmaf(w2, fmaxf(a1, 0.f), s1);
        s2 = fmaf(w2, fmaxf(a2, 0.f), s2);
        s3 = fmaf(w2, fmaxf(a3, 0.f), s3);
    }

    const float bb2 = b2[n];
    const float g0 = 1.f / (1.f + __expf(-(s0 + bb2)));
    const float g1 = 1.f / (1.f + __expf(-(s1 + bb2)));
    const float g2 = 1.f / (1.f + __expf(-(s2 + bb2)));
    const float g3 = 1.f / (1.f + __expf(-(s3 + bb2)));

    const int gy = ty0 + ly;
    float* o = g_weighted + ((size_t)(b * NBR + n) * HH + gy) * WW + tx0 + px;
    float4 w4;
    w4.x = g0 * tC[1][1];
    w4.y = g1 * tC[1][2];
    w4.z = g2 * tC[1][3];
    w4.w = g3 * tC[1][4];
    *reinterpret_cast<float4*>(o) = w4;
}

// ---------------------------------------------------------------------------
// Kernel B: final 7->7 3x3 conv. 128 threads (16x8), 2 px/thread, 32x8 tile.
// Low registers (acc[7][2]) -> ~10 blocks/SM for latency hiding.
// ---------------------------------------------------------------------------
#define TWB 32
#define THB 8

__global__ __launch_bounds__(128) void merge_kernel(
    const float* __restrict__ x,
    const float* __restrict__ Wm,
    const float* __restrict__ bm,
    float* __restrict__ out)
{
    __shared__ float sIn[7][THB + 2][TWB + 4];   // 7 x 10 x 36 (144B rows)
    __shared__ float sW[7][7][12];               // 9 weights padded to 12
    __shared__ float sbm[7];

    const int b   = blockIdx.z;
    const int ty0 = blockIdx.y * THB;
    const int tx0 = blockIdx.x * TWB;
    const int tid = threadIdx.x;

    for (int i = tid; i < 7 * 7 * 9; i += 128) {
        int pair = i / 9, k = i % 9;
        sW[pair / 7][pair % 7][k] = Wm[i];
    }
    if (tid < 7) sbm[tid] = bm[tid];

    const int tile = (THB + 2) * (TWB + 2);      // 10 * 34 = 340
    for (int i = tid; i < 7 * tile; i += 128) {
        int ch  = i / tile;
        int rem = i % tile;
        int r   = rem / (TWB + 2);
        int cc  = rem % (TWB + 2);
        int gy  = ty0 + r - 1;
        int gx  = tx0 + cc - 1;
        float v = 0.0f;
        if (gy >= 0 && gy < HH && gx >= 0 && gx < WW) {
            if (ch == 3) {
                v = x[(size_t)(b * 7 + 3) * (HH * WW) + gy * WW + gx];
            } else {
                int m = (ch < 3) ? ch : (ch - 1);
                v = g_weighted[((size_t)(b * NBR + m) * HH + gy) * WW + gx];
            }
        }
        sIn[ch][r][cc] = v;
    }
    __syncthreads();

    const int lx = tid & 15;
    const int ly = tid >> 4;
    const int px = lx * 2;

    float acc[7][2];
#pragma unroll
    for (int co = 0; co < 7; co++) {
        const float bv = sbm[co];
        acc[co][0] = bv; acc[co][1] = bv;
    }

#pragma unroll
    for (int ci = 0; ci < 7; ci++) {
        float t[3][4];
#pragma unroll
        for (int r = 0; r < 3; r++) {
            const float* rp = &sIn[ci][ly + r][px];     // 8B aligned
            float2 v0 = *reinterpret_cast<const float2*>(rp);
            float2 v1 = *reinterpret_cast<const float2*>(rp + 2);
            t[r][0] = v0.x; t[r][1] = v0.y; t[r][2] = v1.x; t[r][3] = v1.y;
        }

#pragma unroll
        for (int co = 0; co < 7; co++) {
            const float4 wA = *reinterpret_cast<const float4*>(&sW[co][ci][0]);
            const float4 wB = *reinterpret_cast<const float4*>(&sW[co][ci][4]);
            const float4 wC = *reinterpret_cast<const float4*>(&sW[co][ci][8]);
            const float w[9] = {wA.x, wA.y, wA.z, wA.w, wB.x, wB.y, wB.z, wB.w, wC.x};
#pragma unroll
            for (int r = 0; r < 3; r++)
#pragma unroll
                for (int k = 0; k < 3; k++) {
                    const float ww = w[r * 3 + k];
                    acc[co][0] = fmaf(ww, t[r][k],     acc[co][0]);
                    acc[co][1] = fmaf(ww, t[r][k + 1], acc[co][1]);
                }
        }
    }

    const int gy = ty0 + ly;
#pragma unroll
    for (int co = 0; co < 7; co++) {
        float* o = out + ((size_t)(b * 7 + co) * HH + gy) * WW + tx0 + px;
        float2 v2;
        v2.x = acc[co][0]; v2.y = acc[co][1];
        *reinterpret_cast<float2*>(o) = v2;
    }
}

// ---------------------------------------------------------------------------
extern "C" void kernel_launch(void* const* d_in, const int* in_sizes, int n_in,
                              void* d_out, int out_size)
{
    const float* x  = (const float*)d_in[0];   // (8, 7, 256, 256)
    const float* W1 = (const float*)d_in[1];   // (6, 64, 2, 3, 3)
    const float* b1 = (const float*)d_in[2];   // (6, 64)
    const float* W2 = (const float*)d_in[3];   // (6, 1, 64, 1, 1)
    const float* b2 = (const float*)d_in[4];   // (6, 1)
    const float* Wm = (const float*)d_in[5];   // (7, 7, 3, 3)
    const float* bm = (const float*)d_in[6];   // (7,)

    dim3 grid1(WW / TWA, HH / THA, BSZ * NBR);   // 4 x 32 x 48 = 6144
    branch_kernel<<<grid1, 128>>>(x, W1, b1, W2, b2);

    dim3 grid2(WW / TWB, HH / THB, BSZ);         // 8 x 32 x 8 = 2048
    merge_kernel<<<grid2, 128>>>(x, Wm, bm, (float*)d_out);
}

// round 8
// speedup vs baseline: 1.2594x; 1.0138x over previous
#include <cuda_runtime.h>
#include <math.h>

// Problem constants
#define BSZ 8
#define HH 256
#define WW 256
#define C1 64
#define NBR 6

// Scratch: weighted neighbor frames (B, 6, H, W) = 12.6 MB
__device__ float g_weighted[BSZ * NBR * HH * WW];

// ---------------------------------------------------------------------------
// Kernel A: fused conv1(2->64,3x3)+ReLU+conv2(64->1,1x1)+sigmoid+gate
// 128 threads as 16x8; 4 px/thread; tile = 64x8.
// ---------------------------------------------------------------------------
#define TWA 64
#define THA 8

__global__ __launch_bounds__(128) void branch_kernel(
    const float* __restrict__ x,
    const float* __restrict__ W1,
    const float* __restrict__ b1,
    const float* __restrict__ W2,
    const float* __restrict__ b2)
{
    __shared__ float sB[THA + 2][TWA + 4];   // 10 x 68 (272B rows, 16B-aligned)
    __shared__ float sC[THA + 2][TWA + 4];
    // Per-channel packed weights: [0..8]=wb, [9..17]=wc, [18]=b1, [19]=w2, pad->24
    __shared__ float sWp[C1][24];

    const int bz  = blockIdx.z;
    const int b   = bz / NBR;
    const int n   = bz % NBR;
    const int ty0 = blockIdx.y * THA;
    const int tx0 = blockIdx.x * TWA;
    const int tid = threadIdx.x;
    const int lane = tid & 31;
    const int wrp  = tid >> 5;

    const int checkCh = (n < 3) ? n : (n + 1);
    const int bi = (n < 3) ? 0 : 1;   // pair channel that holds base

    const float* __restrict__ base = x + (size_t)(b * 7 + 3) * (HH * WW);
    const float* __restrict__ chk  = x + (size_t)(b * 7 + checkCh) * (HH * WW);

    // Stage packed weights
    for (int i = tid; i < C1 * 9; i += 128) {
        int c = i / 9, k = i - c * 9;
        sWp[c][k]     = W1[((n * C1 + c) * 2 + bi) * 9 + k];
        sWp[c][9 + k] = W1[((n * C1 + c) * 2 + (1 - bi)) * 9 + k];
    }
    if (tid < C1) {
        sWp[tid][18] = b1[n * C1 + tid];
        sWp[tid][19] = W2[n * C1 + tid];
    }

    // Stage input tiles (warp-stripe: warp -> rows, lane -> cols)
    const bool interior = (ty0 > 0) && (ty0 + THA < HH) && (tx0 > 0) && (tx0 + TWA < WW);
    if (interior) {
        for (int r = wrp; r < THA + 2; r += 4) {
            const float* pb = base + (ty0 + r - 1) * WW + (tx0 - 1);
            const float* pc = chk  + (ty0 + r - 1) * WW + (tx0 - 1);
            sB[r][lane]      = pb[lane];
            sB[r][32 + lane] = pb[32 + lane];
            sC[r][lane]      = pc[lane];
            sC[r][32 + lane] = pc[32 + lane];
            if (lane < 2) {
                sB[r][64 + lane] = pb[64 + lane];
                sC[r][64 + lane] = pc[64 + lane];
            }
        }
    } else {
        for (int r = wrp; r < THA + 2; r += 4) {
            const int gy = ty0 + r - 1;
            const bool okY = (gy >= 0) && (gy < HH);
            const float* pb = base + gy * WW;
            const float* pc = chk  + gy * WW;
#pragma unroll
            for (int s = 0; s < 3; s++) {
                int cc = lane + 32 * s;
                if (cc < TWA + 2) {
                    int gx = tx0 + cc - 1;
                    bool ok = okY && (gx >= 0) && (gx < WW);
                    sB[r][cc] = ok ? pb[gx] : 0.0f;
                    sC[r][cc] = ok ? pc[gx] : 0.0f;
                }
            }
        }
    }
    __syncthreads();

    const int lx = tid & 15;
    const int ly = tid >> 4;
    const int px = lx * 4;

    // Register taps: 3 rows x 6 cols per input (4 px + 2 halo)
    float tB[3][6], tC[3][6];
#pragma unroll
    for (int r = 0; r < 3; r++) {
        const float* rb = &sB[ly + r][px];
        const float* rc = &sC[ly + r][px];
        float4 b4 = *reinterpret_cast<const float4*>(rb);
        float2 b2v = *reinterpret_cast<const float2*>(rb + 4);
        float4 c4 = *reinterpret_cast<const float4*>(rc);
        float2 c2 = *reinterpret_cast<const float2*>(rc + 4);
        tB[r][0]=b4.x; tB[r][1]=b4.y; tB[r][2]=b4.z; tB[r][3]=b4.w;
        tB[r][4]=b2v.x; tB[r][5]=b2v.y;
        tC[r][0]=c4.x; tC[r][1]=c4.y; tC[r][2]=c4.z; tC[r][3]=c4.w;
        tC[r][4]=c2.x; tC[r][5]=c2.y;
    }

    float s0 = 0.f, s1 = 0.f, s2 = 0.f, s3 = 0.f;

// One conv tap applied to all 4 px, base (U) + check (V), row R, col K — uses
// vector components DIRECTLY (no float arrays -> no MOV copies on alu pipe)
#define BSTEP(U, V, R, K)                                      \
    a0 = fmaf(U, tB[R][K],     fmaf(V, tC[R][K],     a0));     \
    a1 = fmaf(U, tB[R][K + 1], fmaf(V, tC[R][K + 1], a1));     \
    a2 = fmaf(U, tB[R][K + 2], fmaf(V, tC[R][K + 2], a2));     \
    a3 = fmaf(U, tB[R][K + 3], fmaf(V, tC[R][K + 3], a3));

#pragma unroll 2
    for (int c = 0; c < C1; c++) {
        const float4 wA = *reinterpret_cast<const float4*>(&sWp[c][0]);
        const float4 wB = *reinterpret_cast<const float4*>(&sWp[c][4]);
        const float4 wC = *reinterpret_cast<const float4*>(&sWp[c][8]);
        const float4 wD = *reinterpret_cast<const float4*>(&sWp[c][12]);
        const float4 wE = *reinterpret_cast<const float4*>(&sWp[c][16]);
        // wb[0..8] = wA.x wA.y wA.z wA.w wB.x wB.y wB.z wB.w wC.x
        // wc[0..8] = wC.y wC.z wC.w wD.x wD.y wD.z wD.w wE.x wE.y
        // bias = wE.z, w2 = wE.w

        // k=0 with bias folded in
        float a0 = fmaf(wA.x, tB[0][0], fmaf(wC.y, tC[0][0], wE.z));
        float a1 = fmaf(wA.x, tB[0][1], fmaf(wC.y, tC[0][1], wE.z));
        float a2 = fmaf(wA.x, tB[0][2], fmaf(wC.y, tC[0][2], wE.z));
        float a3 = fmaf(wA.x, tB[0][3], fmaf(wC.y, tC[0][3], wE.z));

        BSTEP(wA.y, wC.z, 0, 1)
        BSTEP(wA.z, wC.w, 0, 2)
        BSTEP(wA.w, wD.x, 1, 0)
        BSTEP(wB.x, wD.y, 1, 1)
        BSTEP(wB.y, wD.z, 1, 2)
        BSTEP(wB.z, wD.w, 2, 0)
        BSTEP(wB.w, wE.x, 2, 1)
        BSTEP(wC.x, wE.y, 2, 2)

        s0 = fmaf(wE.w, fmaxf(a0, 0.f), s0);
        s1 = fmaf(wE.w, fmaxf(a1, 0.f), s1);
        s2 = fmaf(wE.w, fmaxf(a2, 0.f), s2);
        s3 = fmaf(wE.w, fmaxf(a3, 0.f), s3);
    }
#undef BSTEP

    const float bb2 = b2[n];
    const float g0 = 1.f / (1.f + __expf(-(s0 + bb2)));
    const float g1 = 1.f / (1.f + __expf(-(s1 + bb2)));
    const float g2 = 1.f / (1.f + __expf(-(s2 + bb2)));
    const float g3 = 1.f / (1.f + __expf(-(s3 + bb2)));

    const int gy = ty0 + ly;
    float* o = g_weighted + ((size_t)(b * NBR + n) * HH + gy) * WW + tx0 + px;
    float4 w4;
    w4.x = g0 * tC[1][1];
    w4.y = g1 * tC[1][2];
    w4.z = g2 * tC[1][3];
    w4.w = g3 * tC[1][4];
    *reinterpret_cast<float4*>(o) = w4;
}

// ---------------------------------------------------------------------------
// Kernel B: final 7->7 3x3 conv. 128 threads (16x8), 2 px/thread, 32x8 tile.
// Explicit-component FMAs, warp-stripe staging with interior fast path.
// ---------------------------------------------------------------------------
#define TWB 32
#define THB 8

__global__ __launch_bounds__(128) void merge_kernel(
    const float* __restrict__ x,
    const float* __restrict__ Wm,
    const float* __restrict__ bm,
    float* __restrict__ out)
{
    __shared__ float sIn[7][THB + 2][TWB + 4];   // 7 x 10 x 36 (144B rows)
    __shared__ float sW[7][7][12];               // 9 weights padded to 12
    __shared__ float sbm[7];

    const int b   = blockIdx.z;
    const int ty0 = blockIdx.y * THB;
    const int tx0 = blockIdx.x * TWB;
    const int tid = threadIdx.x;
    const int lane = tid & 31;
    const int wrp  = tid >> 5;

    for (int i = tid; i < 7 * 7 * 9; i += 128) {
        int pair = i / 9, k = i - pair * 9;
        sW[pair / 7][pair % 7][k] = Wm[i];
    }
    if (tid < 7) sbm[tid] = bm[tid];

    // Staging: p enumerates (ch, row) pairs; lane covers columns (coalesced)
    const bool interior = (ty0 > 0) && (ty0 + THB < HH) && (tx0 > 0) && (tx0 + TWB < WW);
    const float* __restrict__ xc = x + (size_t)(b * 7 + 3) * (HH * WW);
    const float* __restrict__ gw = g_weighted + (size_t)(b * NBR) * (HH * WW);

    if (interior) {
#pragma unroll 1
        for (int p = wrp; p < 70; p += 4) {
            const int ch = p / 10;
            const int r  = p - ch * 10;
            const float* src;
            if (ch == 3) src = xc;
            else {
                int m = (ch < 3) ? ch : (ch - 1);
                src = gw + (size_t)m * (HH * WW);
            }
            const float* row = src + (ty0 + r - 1) * WW + (tx0 - 1);
            sIn[ch][r][lane] = row[lane];
            if (lane < 2) sIn[ch][r][32 + lane] = row[32 + lane];
        }
    } else {
#pragma unroll 1
        for (int p = wrp; p < 70; p += 4) {
            const int ch = p / 10;
            const int r  = p - ch * 10;
            const float* src;
            if (ch == 3) src = xc;
            else {
                int m = (ch < 3) ? ch : (ch - 1);
                src = gw + (size_t)m * (HH * WW);
            }
            const int gy = ty0 + r - 1;
            const bool okY = (gy >= 0) && (gy < HH);
            const int gx0 = tx0 - 1 + lane;
            float v0 = 0.f;
            if (okY && gx0 >= 0 && gx0 < WW) v0 = src[gy * WW + gx0];
            sIn[ch][r][lane] = v0;
            if (lane < 2) {
                const int gx1 = gx0 + 32;
                float v1 = 0.f;
                if (okY && gx1 >= 0 && gx1 < WW) v1 = src[gy * WW + gx1];
                sIn[ch][r][32 + lane] = v1;
            }
        }
    }
    __syncthreads();

    const int lx = tid & 15;
    const int ly = tid >> 4;
    const int px = lx * 2;

    float acc0[7], acc1[7];
#pragma unroll
    for (int co = 0; co < 7; co++) { acc0[co] = sbm[co]; acc1[co] = acc0[co]; }

#pragma unroll
    for (int ci = 0; ci < 7; ci++) {
        // Taps: 3 rows x 4 cols as float2 pairs (components used directly)
        const float2 r0a = *reinterpret_cast<const float2*>(&sIn[ci][ly + 0][px]);
        const float2 r0b = *reinterpret_cast<const float2*>(&sIn[ci][ly + 0][px + 2]);
        const float2 r1a = *reinterpret_cast<const float2*>(&sIn[ci][ly + 1][px]);
        const float2 r1b = *reinterpret_cast<const float2*>(&sIn[ci][ly + 1][px + 2]);
        const float2 r2a = *reinterpret_cast<const float2*>(&sIn[ci][ly + 2][px]);
        const float2 r2b = *reinterpret_cast<const float2*>(&sIn[ci][ly + 2][px + 2]);

#pragma unroll
        for (int co = 0; co < 7; co++) {
            const float4 wA = *reinterpret_cast<const float4*>(&sW[co][ci][0]);
            const float4 wB = *reinterpret_cast<const float4*>(&sW[co][ci][4]);
            const float  w8 = sW[co][ci][8];
            // row0: wA.x wA.y wA.z ; row1: wA.w wB.x wB.y ; row2: wB.z wB.w w8
            float p0 = acc0[co], p1 = acc1[co];
            p0 = fmaf(wA.x, r0a.x, p0);  p1 = fmaf(wA.x, r0a.y, p1);
            p0 = fmaf(wA.y, r0a.y, p0);  p1 = fmaf(wA.y, r0b.x, p1);
            p0 = fmaf(wA.z, r0b.x, p0);  p1 = fmaf(wA.z, r0b.y, p1);
            p0 = fmaf(wA.w, r1a.x, p0);  p1 = fmaf(wA.w, r1a.y, p1);
            p0 = fmaf(wB.x, r1a.y, p0);  p1 = fmaf(wB.x, r1b.x, p1);
            p0 = fmaf(wB.y, r1b.x, p0);  p1 = fmaf(wB.y, r1b.y, p1);
            p0 = fmaf(wB.z, r2a.x, p0);  p1 = fmaf(wB.z, r2a.y, p1);
            p0 = fmaf(wB.w, r2a.y, p0);  p1 = fmaf(wB.w, r2b.x, p1);
            p0 = fmaf(w8,   r2b.x, p0);  p1 = fmaf(w8,   r2b.y, p1);
            acc0[co] = p0; acc1[co] = p1;
        }
    }

    const int gy = ty0 + ly;
#pragma unroll
    for (int co = 0; co < 7; co++) {
        float* o = out + ((size_t)(b * 7 + co) * HH + gy) * WW + tx0 + px;
        float2 v2;
        v2.x = acc0[co]; v2.y = acc1[co];
        *reinterpret_cast<float2*>(o) = v2;
    }
}

// ---------------------------------------------------------------------------
extern "C" void kernel_launch(void* const* d_in, const int* in_sizes, int n_in,
                              void* d_out, int out_size)
{
    const float* x  = (const float*)d_in[0];   // (8, 7, 256, 256)
    const float* W1 = (const float*)d_in[1];   // (6, 64, 2, 3, 3)
    const float* b1 = (const float*)d_in[2];   // (6, 64)
    const float* W2 = (const float*)d_in[3];   // (6, 1, 64, 1, 1)
    const float* b2 = (const float*)d_in[4];   // (6, 1)
    const float* Wm = (const float*)d_in[5];   // (7, 7, 3, 3)
    const float* bm = (const float*)d_in[6];   // (7,)

    dim3 grid1(WW / TWA, HH / THA, BSZ * NBR);   // 4 x 32 x 48 = 6144
    branch_kernel<<<grid1, 128>>>(x, W1, b1, W2, b2);

    dim3 grid2(WW / TWB, HH / THB, BSZ);         // 8 x 32 x 8 = 2048
    merge_kernel<<<grid2, 128>>>(x, Wm, bm, (float*)d_out);
}